// round 2
// baseline (speedup 1.0000x reference)
#include <cuda_runtime.h>
#include <math.h>

#define N_NODES 100000
#define N_EDGES 1600000
#define HALF_E  (N_EDGES / 2)

typedef unsigned long long u64;

// scratch (static device arrays; no allocation at runtime)
__device__ float g_dot[N_EDGES];
__device__ float g_m[N_NODES];
__device__ float g_s[N_NODES];

// ---- packed f32x2 helpers (sm_103a FFMA2 path) ----
__device__ __forceinline__ u64 pk(float lo, float hi) {
    u64 r; asm("mov.b64 %0,{%1,%2};" : "=l"(r) : "f"(lo), "f"(hi)); return r;
}
__device__ __forceinline__ void upk(u64 x, float& lo, float& hi) {
    asm("mov.b64 {%0,%1},%2;" : "=f"(lo), "=f"(hi) : "l"(x));
}
__device__ __forceinline__ u64 fma2(u64 a, u64 b, u64 c) {
    u64 d; asm("fma.rn.f32x2 %0,%1,%2,%3;" : "=l"(d) : "l"(a), "l"(b), "l"(c)); return d;
}
__device__ __forceinline__ u64 add2(u64 a, u64 b) {
    u64 d; asm("add.rn.f32x2 %0,%1,%2;" : "=l"(d) : "l"(a), "l"(b)); return d;
}
__device__ __forceinline__ u64 mul2(u64 a, u64 b) {
    u64 d; asm("mul.rn.f32x2 %0,%1,%2;" : "=l"(d) : "l"(a), "l"(b)); return d;
}

#define C_NEG1      0xBF800000BF800000ull   // (-1.f, -1.f)
#define C_SIXTEENTH 0x3D8000003D800000ull   // (0.0625f, 0.0625f)

struct SWP {
    u64 W1[4][3][16];
    u64 b1[4][16], g1[4][16], be1[4][16];
    u64 W2[4][16][16];
    u64 b2[4][16], g2[4][16], be2[4][16];
    u64 W3a[3][16][4];   // W3_00, W3_01, W3_10
    u64 b3a[3][4];
    u64 W3_11[16][12];
    u64 b3_11[12];
    u64 wq[8];           // [2][2][2]
};

__device__ __forceinline__ void ln_relu_pk(u64* h, const u64* g, const u64* be) {
    u64 s = h[0];
#pragma unroll
    for (int j = 1; j < 16; j++) s = add2(s, h[j]);
    u64 mu = mul2(s, C_SIXTEENTH);
    u64 vs = 0ull;
#pragma unroll
    for (int j = 0; j < 16; j++) {
        h[j] = fma2(mu, C_NEG1, h[j]);      // h <- h - mu
        vs = fma2(h[j], h[j], vs);
    }
    float vlo, vhi;
    upk(vs, vlo, vhi);
    float ilo = rsqrtf(fmaf(vlo, 0.0625f, 1e-5f));
    float ihi = rsqrtf(fmaf(vhi, 0.0625f, 1e-5f));
    u64 inv = pk(ilo, ihi);
#pragma unroll
    for (int j = 0; j < 16; j++) {
        u64 t = mul2(h[j], inv);
        u64 val = fma2(t, g[j], be[j]);
        float a, b;
        upk(val, a, b);
        h[j] = pk(fmaxf(a, 0.f), fmaxf(b, 0.f));
    }
}

template <int OUT>
__device__ __forceinline__ void radial_pk(const SWP& sw, int i, const u64* W3, const u64* b3,
                                          u64 v0, u64 v1, u64 v2, u64* R) {
    u64 h[16];
#pragma unroll
    for (int j = 0; j < 16; j++)
        h[j] = fma2(v0, sw.W1[i][0][j],
               fma2(v1, sw.W1[i][1][j],
               fma2(v2, sw.W1[i][2][j], sw.b1[i][j])));
    ln_relu_pk(h, sw.g1[i], sw.be1[i]);
    u64 h2[16];
#pragma unroll
    for (int j = 0; j < 16; j++) {
        u64 acc = sw.b2[i][j];
#pragma unroll
        for (int k = 0; k < 16; k++) acc = fma2(h[k], sw.W2[i][k][j], acc);
        h2[j] = acc;
    }
    ln_relu_pk(h2, sw.g2[i], sw.be2[i]);
#pragma unroll
    for (int o = 0; o < OUT; o++) {
        u64 acc = b3[o];
#pragma unroll
        for (int k = 0; k < 16; k++) acc = fma2(h2[k], W3[k * OUT + o], acc);
        R[o] = acc;
    }
}

__device__ __forceinline__ void atomicMaxF(float* addr, float val) {
    if (val >= 0.f) atomicMax((int*)addr, __float_as_int(val));
    else            atomicMin((unsigned int*)addr, __float_as_uint(val));
}

__global__ void init_kernel() {
    int n = blockIdx.x * blockDim.x + threadIdx.x;
    if (n < N_NODES) {
        g_m[n] = -INFINITY;
        g_s[n] = 0.f;
    }
}

__global__ __launch_bounds__(256) void edge_kernel(
    const float* __restrict__ f0, const float* __restrict__ f1,
    const float* __restrict__ dist,
    const int* __restrict__ u, const int* __restrict__ v,
    const float* __restrict__ wq,
    const float* __restrict__ wj00, const float* __restrict__ wj01,
    const float* __restrict__ wj10, const float* __restrict__ wj11,
    const float* __restrict__ rW1, const float* __restrict__ rb1,
    const float* __restrict__ g1, const float* __restrict__ be1,
    const float* __restrict__ rW2, const float* __restrict__ rb2,
    const float* __restrict__ g2, const float* __restrict__ be2,
    const float* __restrict__ W3_00, const float* __restrict__ b3_00,
    const float* __restrict__ W3_01, const float* __restrict__ b3_01,
    const float* __restrict__ W3_10, const float* __restrict__ b3_10,
    const float* __restrict__ W3_11, const float* __restrict__ b3_11)
{
    __shared__ SWP sw;
    {
        int t = threadIdx.x;
#define CPYP(dst, src, n) for (int i = t; i < (n); i += 256) ((u64*)(dst))[i] = pk((src)[i], (src)[i])
        CPYP(sw.W1, rW1, 192);
        CPYP(sw.b1, rb1, 64);
        CPYP(sw.g1, g1, 64);
        CPYP(sw.be1, be1, 64);
        CPYP(sw.W2, rW2, 1024);
        CPYP(sw.b2, rb2, 64);
        CPYP(sw.g2, g2, 64);
        CPYP(sw.be2, be2, 64);
        CPYP(sw.W3a[0], W3_00, 64);
        CPYP(sw.W3a[1], W3_01, 64);
        CPYP(sw.W3a[2], W3_10, 64);
        CPYP(sw.b3a[0], b3_00, 4);
        CPYP(sw.b3a[1], b3_01, 4);
        CPYP(sw.b3a[2], b3_10, 4);
        CPYP(sw.W3_11, W3_11, 192);
        CPYP(sw.b3_11, b3_11, 12);
        CPYP(sw.wq, wq, 8);
#undef CPYP
    }
    __syncthreads();

    int e0 = blockIdx.x * blockDim.x + threadIdx.x;
    if (e0 >= HALF_E) return;
    int e1 = e0 + HALF_E;

    int u0 = u[e0], u1 = u[e1];
    int n0 = v[e0], n1 = v[e1];

    u64 f0u0 = pk(f0[2 * u0],     f0[2 * u1]);
    u64 f0u1 = pk(f0[2 * u0 + 1], f0[2 * u1 + 1]);
    u64 f0v0 = pk(f0[2 * n0],     f0[2 * n1]);
    u64 f0v1 = pk(f0[2 * n0 + 1], f0[2 * n1 + 1]);
    u64 f1v[6];
#pragma unroll
    for (int i = 0; i < 6; i++) f1v[i] = pk(f1[6 * n0 + i], f1[6 * n1 + i]);

    u64 vv0 = mul2(f0u0, f0v0);
    u64 vv1 = mul2(f0u1, f0v1);
    u64 vv2 = pk(dist[e0], dist[e1]);

    u64 R[12];

    // (l=0,k=0)  i=0
    radial_pk<4>(sw, 0, (const u64*)sw.W3a[0], sw.b3a[0], vv0, vv1, vv2, R);
    u64 wj00p = pk(wj00[e0], wj00[e1]);
    u64 k0_0 = mul2(wj00p, fma2(R[0], f0v0, mul2(R[1], f0v1)));
    u64 k0_1 = mul2(wj00p, fma2(R[2], f0v0, mul2(R[3], f0v1)));

    // (l=0,k=1)  i=1
    radial_pk<4>(sw, 1, (const u64*)sw.W3a[1], sw.b3a[1], vv0, vv1, vv2, R);
    {
        u64 w0 = pk(wj01[3 * e0 + 0], wj01[3 * e1 + 0]);
        u64 w1 = pk(wj01[3 * e0 + 1], wj01[3 * e1 + 1]);
        u64 w2 = pk(wj01[3 * e0 + 2], wj01[3 * e1 + 2]);
        u64 t0 = fma2(w0, f1v[0], fma2(w1, f1v[1], mul2(w2, f1v[2])));
        u64 t1 = fma2(w0, f1v[3], fma2(w1, f1v[4], mul2(w2, f1v[5])));
        k0_0 = fma2(R[0], t0, fma2(R[1], t1, k0_0));
        k0_1 = fma2(R[2], t0, fma2(R[3], t1, k0_1));
    }

    // (l=1,k=0)  i=2
    u64 k1[2][3];
    radial_pk<4>(sw, 2, (const u64*)sw.W3a[2], sw.b3a[2], vv0, vv1, vv2, R);
    {
        u64 d0 = fma2(R[0], f0v0, mul2(R[1], f0v1));
        u64 d1 = fma2(R[2], f0v0, mul2(R[3], f0v1));
#pragma unroll
        for (int l = 0; l < 3; l++) {
            u64 w = pk(wj10[3 * e0 + l], wj10[3 * e1 + l]);
            k1[0][l] = mul2(d0, w);
            k1[1][l] = mul2(d1, w);
        }
    }

    // (l=1,k=1)  i=3 : R reshaped [3(j)][2(o)][2(i)], wj11 [3(j)][3(l)][3(kk)]
    radial_pk<12>(sw, 3, (const u64*)sw.W3_11, sw.b3_11, vv0, vv1, vv2, R);
#pragma unroll
    for (int j = 0; j < 3; j++) {
        u64 w[9];
#pragma unroll
        for (int x = 0; x < 9; x++)
            w[x] = pk(wj11[27 * e0 + 9 * j + x], wj11[27 * e1 + 9 * j + x]);
#pragma unroll
        for (int l = 0; l < 3; l++) {
            u64 s0 = fma2(w[3 * l], f1v[0], fma2(w[3 * l + 1], f1v[1], mul2(w[3 * l + 2], f1v[2])));
            u64 s1 = fma2(w[3 * l], f1v[3], fma2(w[3 * l + 1], f1v[4], mul2(w[3 * l + 2], f1v[5])));
            k1[0][l] = fma2(R[4 * j + 0], s0, fma2(R[4 * j + 1], s1, k1[0][l]));
            k1[1][l] = fma2(R[4 * j + 2], s0, fma2(R[4 * j + 3], s1, k1[1][l]));
        }
    }

    // q[v] and dot   (wq linear index [p][o][i] = p*4 + o*2 + i)
    u64 dotp = 0ull;
#pragma unroll
    for (int o = 0; o < 2; o++) {
        u64 q0 = fma2(sw.wq[o * 2 + 0], f0v0, mul2(sw.wq[o * 2 + 1], f0v1));
        dotp = fma2(q0, (o == 0 ? k0_0 : k0_1), dotp);
#pragma unroll
        for (int m = 0; m < 3; m++) {
            u64 q1 = fma2(sw.wq[4 + o * 2 + 0], f1v[m], mul2(sw.wq[4 + o * 2 + 1], f1v[3 + m]));
            dotp = fma2(q1, k1[o][m], dotp);
        }
    }

    float dlo, dhi;
    upk(dotp, dlo, dhi);
    g_dot[e0] = dlo;
    g_dot[e1] = dhi;
    atomicMaxF(&g_m[n0], dlo);
    atomicMaxF(&g_m[n1], dhi);
}

__global__ void exp_kernel(const int* __restrict__ v, float* __restrict__ out) {
    int e = blockIdx.x * blockDim.x + threadIdx.x;
    if (e >= N_EDGES) return;
    int vv = v[e];
    float p = expf(g_dot[e] - g_m[vv]);
    out[e] = p;
    atomicAdd(&g_s[vv], p);
}

__global__ void norm_kernel(const int* __restrict__ v, float* __restrict__ out) {
    int e = blockIdx.x * blockDim.x + threadIdx.x;
    if (e >= N_EDGES) return;
    out[e] = out[e] / g_s[v[e]];
}

extern "C" void kernel_launch(void* const* d_in, const int* in_sizes, int n_in,
                              void* d_out, int out_size) {
    const float* f0    = (const float*)d_in[0];
    const float* f1    = (const float*)d_in[1];
    const float* dist  = (const float*)d_in[2];
    const int*   u     = (const int*)d_in[3];
    const int*   v     = (const int*)d_in[4];
    const float* wq    = (const float*)d_in[5];
    const float* wj00  = (const float*)d_in[6];
    const float* wj01  = (const float*)d_in[7];
    const float* wj10  = (const float*)d_in[8];
    const float* wj11  = (const float*)d_in[9];
    const float* rW1   = (const float*)d_in[10];
    const float* rb1   = (const float*)d_in[11];
    const float* g1    = (const float*)d_in[12];
    const float* be1   = (const float*)d_in[13];
    const float* rW2   = (const float*)d_in[14];
    const float* rb2   = (const float*)d_in[15];
    const float* g2    = (const float*)d_in[16];
    const float* be2   = (const float*)d_in[17];
    const float* W3_00 = (const float*)d_in[18];
    const float* b3_00 = (const float*)d_in[19];
    const float* W3_01 = (const float*)d_in[20];
    const float* b3_01 = (const float*)d_in[21];
    const float* W3_10 = (const float*)d_in[22];
    const float* b3_10 = (const float*)d_in[23];
    const float* W3_11 = (const float*)d_in[24];
    const float* b3_11 = (const float*)d_in[25];
    float* out = (float*)d_out;

    init_kernel<<<(N_NODES + 255) / 256, 256>>>();
    edge_kernel<<<(HALF_E + 255) / 256, 256>>>(
        f0, f1, dist, u, v, wq, wj00, wj01, wj10, wj11,
        rW1, rb1, g1, be1, rW2, rb2, g2, be2,
        W3_00, b3_00, W3_01, b3_01, W3_10, b3_10, W3_11, b3_11);
    exp_kernel<<<(N_EDGES + 255) / 256, 256>>>(v, out);
    norm_kernel<<<(N_EDGES + 255) / 256, 256>>>(v, out);
}

// round 5
// speedup vs baseline: 1.1876x; 1.1876x over previous
#include <cuda_runtime.h>
#include <math.h>

#define N_NODES 100000
#define N_EDGES 1600000
#define HALF_E  (N_EDGES / 2)

typedef unsigned long long u64;

__device__ float g_dot[N_EDGES];
__device__ float g_m[N_NODES];
__device__ float g_s[N_NODES];

// ---- packed f32x2 helpers ----
union PU { u64 u; float2 f; };

__device__ __forceinline__ u64 pk(float lo, float hi) {
    PU p; p.f.x = lo; p.f.y = hi; return p.u;
}
__device__ __forceinline__ float2 upk2(u64 x) { PU p; p.u = x; return p.f; }

__device__ __forceinline__ u64 fma2(u64 a, u64 b, u64 c) {
    u64 d; asm("fma.rn.f32x2 %0,%1,%2,%3;" : "=l"(d) : "l"(a), "l"(b), "l"(c)); return d;
}
__device__ __forceinline__ u64 add2(u64 a, u64 b) {
    u64 d; asm("add.rn.f32x2 %0,%1,%2;" : "=l"(d) : "l"(a), "l"(b)); return d;
}
__device__ __forceinline__ u64 mul2(u64 a, u64 b) {
    u64 d; asm("mul.rn.f32x2 %0,%1,%2;" : "=l"(d) : "l"(a), "l"(b)); return d;
}

#define C_NEG1      0xBF800000BF800000ull   // (-1.f, -1.f)
#define C_SIXTEENTH 0x3D8000003D800000ull   // (0.0625f, 0.0625f)

struct SWP {
    u64 W1[4][3][16];
    u64 b1[4][16], g1[4][16], be1[4][16];
    u64 W2[4][16][16];
    u64 b2[4][16], g2[4][16], be2[4][16];
    u64 W3a[3][16][4];   // W3_00, W3_01, W3_10
    u64 b3a[3][4];
    u64 W3_11[16][12];
    u64 b3_11[12];
    float wqs[8];        // scalar wq [2][2][2]
};

// numerically safe LN: subtract mean first, then square (matches reference)
__device__ __forceinline__ void ln_relu_pk(u64* h, const u64* g, const u64* be) {
    u64 s = h[0];
#pragma unroll
    for (int j = 1; j < 16; j++) s = add2(s, h[j]);
    u64 mu = mul2(s, C_SIXTEENTH);
    u64 vs = 0ull;
#pragma unroll
    for (int j = 0; j < 16; j++) {
        h[j] = fma2(mu, C_NEG1, h[j]);      // h <- h - mu
        vs = fma2(h[j], h[j], vs);
    }
    float2 V = upk2(vs);
    u64 inv = pk(rsqrtf(fmaf(V.x, 0.0625f, 1e-5f)),
                 rsqrtf(fmaf(V.y, 0.0625f, 1e-5f)));
#pragma unroll
    for (int j = 0; j < 16; j++) {
        u64 tj = mul2(h[j], inv);
        PU val; val.u = fma2(tj, g[j], be[j]);
        val.f.x = fmaxf(val.f.x, 0.f);
        val.f.y = fmaxf(val.f.y, 0.f);
        h[j] = val.u;
    }
}

template <int OUT>
__device__ __forceinline__ void radial_pk(const SWP& sw, int i, const u64* W3, const u64* b3,
                                          u64 va, u64 vb, u64 vc, u64* R) {
    u64 h[16];
#pragma unroll
    for (int j = 0; j < 16; j++)
        h[j] = fma2(va, sw.W1[i][0][j],
               fma2(vb, sw.W1[i][1][j],
               fma2(vc, sw.W1[i][2][j], sw.b1[i][j])));
    ln_relu_pk(h, sw.g1[i], sw.be1[i]);
    u64 h2[16];
#pragma unroll
    for (int j = 0; j < 16; j++) {
        u64 acc = sw.b2[i][j];
#pragma unroll
        for (int k = 0; k < 16; k++) acc = fma2(h[k], sw.W2[i][k][j], acc);
        h2[j] = acc;
    }
    ln_relu_pk(h2, sw.g2[i], sw.be2[i]);
#pragma unroll
    for (int o = 0; o < OUT; o++) {
        u64 acc = b3[o];
#pragma unroll
        for (int k = 0; k < 16; k++) acc = fma2(h2[k], W3[k * OUT + o], acc);
        R[o] = acc;
    }
}

__device__ __forceinline__ void atomicMaxF(float* addr, float val) {
    if (val >= 0.f) atomicMax((int*)addr, __float_as_int(val));
    else            atomicMin((unsigned int*)addr, __float_as_uint(val));
}

__global__ void init_kernel() {
    int n = blockIdx.x * blockDim.x + threadIdx.x;
    if (n < N_NODES) {
        g_m[n] = -INFINITY;
        g_s[n] = 0.f;
    }
}

__global__ __launch_bounds__(128, 3) void edge_kernel(
    const float* __restrict__ f0, const float* __restrict__ f1,
    const float* __restrict__ dist,
    const int* __restrict__ u, const int* __restrict__ v,
    const float* __restrict__ wq,
    const float* __restrict__ wj00, const float* __restrict__ wj01,
    const float* __restrict__ wj10, const float* __restrict__ wj11,
    const float* __restrict__ rW1, const float* __restrict__ rb1,
    const float* __restrict__ g1, const float* __restrict__ be1,
    const float* __restrict__ rW2, const float* __restrict__ rb2,
    const float* __restrict__ g2, const float* __restrict__ be2,
    const float* __restrict__ W3_00, const float* __restrict__ b3_00,
    const float* __restrict__ W3_01, const float* __restrict__ b3_01,
    const float* __restrict__ W3_10, const float* __restrict__ b3_10,
    const float* __restrict__ W3_11, const float* __restrict__ b3_11)
{
    __shared__ SWP sw;
    {
        int t = threadIdx.x;
#define CPYP(dst, src, n) for (int i = t; i < (n); i += 128) ((u64*)(dst))[i] = pk((src)[i], (src)[i])
        CPYP(sw.W1, rW1, 192);
        CPYP(sw.b1, rb1, 64);
        CPYP(sw.g1, g1, 64);
        CPYP(sw.be1, be1, 64);
        CPYP(sw.W2, rW2, 1024);
        CPYP(sw.b2, rb2, 64);
        CPYP(sw.g2, g2, 64);
        CPYP(sw.be2, be2, 64);
        CPYP(sw.W3a[0], W3_00, 64);
        CPYP(sw.W3a[1], W3_01, 64);
        CPYP(sw.W3a[2], W3_10, 64);
        CPYP(sw.b3a[0], b3_00, 4);
        CPYP(sw.b3a[1], b3_01, 4);
        CPYP(sw.b3a[2], b3_10, 4);
        CPYP(sw.W3_11, W3_11, 192);
        CPYP(sw.b3_11, b3_11, 12);
#undef CPYP
        for (int i = t; i < 8; i += 128) sw.wqs[i] = wq[i];
    }
    __syncthreads();

    int t = blockIdx.x * 128 + threadIdx.x;   // grid exactly HALF_E/128; edges 2t, 2t+1

    int2 uu = ((const int2*)u)[t];
    int2 vv = ((const int2*)v)[t];
    float2 dd = ((const float2*)dist)[t];

    float2 fu_a = ((const float2*)f0)[uu.x];
    float2 fu_b = ((const float2*)f0)[uu.y];
    float2 fv_a = ((const float2*)f0)[vv.x];
    float2 fv_b = ((const float2*)f0)[vv.y];

    float f1a[6], f1b[6];
    {
        const float2* p0 = (const float2*)f1 + 3 * vv.x;
        const float2* p1 = (const float2*)f1 + 3 * vv.y;
        float2 x;
        x = p0[0]; f1a[0] = x.x; f1a[1] = x.y;
        x = p0[1]; f1a[2] = x.x; f1a[3] = x.y;
        x = p0[2]; f1a[4] = x.x; f1a[5] = x.y;
        x = p1[0]; f1b[0] = x.x; f1b[1] = x.y;
        x = p1[1]; f1b[2] = x.x; f1b[3] = x.y;
        x = p1[2]; f1b[4] = x.x; f1b[5] = x.y;
    }

    u64 va = pk(fu_a.x * fv_a.x, fu_b.x * fv_b.x);
    u64 vb = pk(fu_a.y * fv_a.y, fu_b.y * fv_b.y);
    u64 vc = pk(dd.x, dd.y);

    u64 Rp[12];
    float k00[2], k01[2];        // l=0 accumulators, per edge, per o
    float k1[2][2][3];           // [edge][o][l]

    // ---- i=0 (l=0,k=0) ----
    radial_pk<4>(sw, 0, (const u64*)sw.W3a[0], sw.b3a[0], va, vb, vc, Rp);
    {
        float2 w00 = ((const float2*)wj00)[t];
        float2 r0 = upk2(Rp[0]), r1 = upk2(Rp[1]), r2 = upk2(Rp[2]), r3 = upk2(Rp[3]);
        k00[0] = w00.x * fmaf(r0.x, fv_a.x, r1.x * fv_a.y);
        k01[0] = w00.x * fmaf(r2.x, fv_a.x, r3.x * fv_a.y);
        k00[1] = w00.y * fmaf(r0.y, fv_b.x, r1.y * fv_b.y);
        k01[1] = w00.y * fmaf(r2.y, fv_b.x, r3.y * fv_b.y);
    }

    // ---- i=1 (l=0,k=1) ----
    radial_pk<4>(sw, 1, (const u64*)sw.W3a[1], sw.b3a[1], va, vb, vc, Rp);
    {
        const float2* wp = (const float2*)wj01;
        float2 a = wp[3 * t], b = wp[3 * t + 1], c = wp[3 * t + 2];
        float2 r0 = upk2(Rp[0]), r1 = upk2(Rp[1]), r2 = upk2(Rp[2]), r3 = upk2(Rp[3]);
        {   // edge 0: w = {a.x, a.y, b.x}
            float t0 = fmaf(a.x, f1a[0], fmaf(a.y, f1a[1], b.x * f1a[2]));
            float t1 = fmaf(a.x, f1a[3], fmaf(a.y, f1a[4], b.x * f1a[5]));
            k00[0] = fmaf(r0.x, t0, fmaf(r1.x, t1, k00[0]));
            k01[0] = fmaf(r2.x, t0, fmaf(r3.x, t1, k01[0]));
        }
        {   // edge 1: w = {b.y, c.x, c.y}
            float t0 = fmaf(b.y, f1b[0], fmaf(c.x, f1b[1], c.y * f1b[2]));
            float t1 = fmaf(b.y, f1b[3], fmaf(c.x, f1b[4], c.y * f1b[5]));
            k00[1] = fmaf(r0.y, t0, fmaf(r1.y, t1, k00[1]));
            k01[1] = fmaf(r2.y, t0, fmaf(r3.y, t1, k01[1]));
        }
    }

    // ---- i=2 (l=1,k=0) ----
    radial_pk<4>(sw, 2, (const u64*)sw.W3a[2], sw.b3a[2], va, vb, vc, Rp);
    {
        const float2* wp = (const float2*)wj10;
        float2 a = wp[3 * t], b = wp[3 * t + 1], c = wp[3 * t + 2];
        float2 r0 = upk2(Rp[0]), r1 = upk2(Rp[1]), r2 = upk2(Rp[2]), r3 = upk2(Rp[3]);
        float d0 = fmaf(r0.x, fv_a.x, r1.x * fv_a.y);
        float d1 = fmaf(r2.x, fv_a.x, r3.x * fv_a.y);
        float e0w[3] = {a.x, a.y, b.x};
        float e1w[3] = {b.y, c.x, c.y};
#pragma unroll
        for (int l = 0; l < 3; l++) { k1[0][0][l] = d0 * e0w[l]; k1[0][1][l] = d1 * e0w[l]; }
        float d0b = fmaf(r0.y, fv_b.x, r1.y * fv_b.y);
        float d1b = fmaf(r2.y, fv_b.x, r3.y * fv_b.y);
#pragma unroll
        for (int l = 0; l < 3; l++) { k1[1][0][l] = d0b * e1w[l]; k1[1][1][l] = d1b * e1w[l]; }
    }

    // ---- i=3 (l=1,k=1) ----
    radial_pk<12>(sw, 3, (const u64*)sw.W3_11, sw.b3_11, va, vb, vc, Rp);
    {
        const float2* wp = (const float2*)wj11;
#pragma unroll
        for (int p = 0; p < 2; p++) {
            float w27[27];
            if (p == 0) {
#pragma unroll
                for (int k = 0; k < 13; k++) {
                    float2 x = wp[27 * t + k];
                    w27[2 * k] = x.x; w27[2 * k + 1] = x.y;
                }
                w27[26] = wj11[54 * t + 26];
            } else {
                w27[0] = wj11[54 * t + 27];
#pragma unroll
                for (int k = 0; k < 13; k++) {
                    float2 x = wp[27 * t + 14 + k];
                    w27[2 * k + 1] = x.x; w27[2 * k + 2] = x.y;
                }
            }
            const float* f1p = (p == 0) ? f1a : f1b;
#pragma unroll
            for (int j = 0; j < 3; j++) {
                float2 R0 = upk2(Rp[4 * j + 0]), R1 = upk2(Rp[4 * j + 1]);
                float2 R2 = upk2(Rp[4 * j + 2]), R3 = upk2(Rp[4 * j + 3]);
                float r0 = (p == 0) ? R0.x : R0.y;
                float r1 = (p == 0) ? R1.x : R1.y;
                float r2 = (p == 0) ? R2.x : R2.y;
                float r3 = (p == 0) ? R3.x : R3.y;
#pragma unroll
                for (int l = 0; l < 3; l++) {
                    float s0 = fmaf(w27[9 * j + 3 * l], f1p[0],
                               fmaf(w27[9 * j + 3 * l + 1], f1p[1], w27[9 * j + 3 * l + 2] * f1p[2]));
                    float s1 = fmaf(w27[9 * j + 3 * l], f1p[3],
                               fmaf(w27[9 * j + 3 * l + 1], f1p[4], w27[9 * j + 3 * l + 2] * f1p[5]));
                    k1[p][0][l] = fmaf(r0, s0, fmaf(r1, s1, k1[p][0][l]));
                    k1[p][1][l] = fmaf(r2, s0, fmaf(r3, s1, k1[p][1][l]));
                }
            }
        }
    }

    // ---- q·k dot, store, atomicMax ----
    float dots[2];
#pragma unroll
    for (int p = 0; p < 2; p++) {
        float2 fv = (p == 0) ? fv_a : fv_b;
        const float* f1p = (p == 0) ? f1a : f1b;
        float dot = 0.f;
#pragma unroll
        for (int o = 0; o < 2; o++) {
            float q0 = fmaf(sw.wqs[o * 2 + 0], fv.x, sw.wqs[o * 2 + 1] * fv.y);
            dot = fmaf(q0, (o == 0 ? k00[p] : k01[p]), dot);
#pragma unroll
            for (int m = 0; m < 3; m++) {
                float q1 = fmaf(sw.wqs[4 + o * 2 + 0], f1p[m], sw.wqs[4 + o * 2 + 1] * f1p[3 + m]);
                dot = fmaf(q1, k1[p][o][m], dot);
            }
        }
        dots[p] = dot;
    }

    float2 dw; dw.x = dots[0]; dw.y = dots[1];
    ((float2*)g_dot)[t] = dw;
    atomicMaxF(&g_m[vv.x], dots[0]);
    atomicMaxF(&g_m[vv.y], dots[1]);
}

__global__ void exp_kernel(const int* __restrict__ v, float* __restrict__ out) {
    int e = blockIdx.x * 256 + threadIdx.x;
    if (e >= N_EDGES) return;
    int vv = v[e];
    float p = __expf(g_dot[e] - g_m[vv]);
    out[e] = p;
    atomicAdd(&g_s[vv], p);
}

__global__ void norm_kernel(const int* __restrict__ v, float* __restrict__ out) {
    int t = blockIdx.x * 256 + threadIdx.x;
    if (t >= HALF_E) return;
    int2 vv = ((const int2*)v)[t];
    float2 o = ((const float2*)out)[t];
    o.x = o.x / g_s[vv.x];
    o.y = o.y / g_s[vv.y];
    ((float2*)out)[t] = o;
}

extern "C" void kernel_launch(void* const* d_in, const int* in_sizes, int n_in,
                              void* d_out, int out_size) {
    const float* f0    = (const float*)d_in[0];
    const float* f1    = (const float*)d_in[1];
    const float* dist  = (const float*)d_in[2];
    const int*   u     = (const int*)d_in[3];
    const int*   v     = (const int*)d_in[4];
    const float* wq    = (const float*)d_in[5];
    const float* wj00  = (const float*)d_in[6];
    const float* wj01  = (const float*)d_in[7];
    const float* wj10  = (const float*)d_in[8];
    const float* wj11  = (const float*)d_in[9];
    const float* rW1   = (const float*)d_in[10];
    const float* rb1   = (const float*)d_in[11];
    const float* g1    = (const float*)d_in[12];
    const float* be1   = (const float*)d_in[13];
    const float* rW2   = (const float*)d_in[14];
    const float* rb2   = (const float*)d_in[15];
    const float* g2    = (const float*)d_in[16];
    const float* be2   = (const float*)d_in[17];
    const float* W3_00 = (const float*)d_in[18];
    const float* b3_00 = (const float*)d_in[19];
    const float* W3_01 = (const float*)d_in[20];
    const float* b3_01 = (const float*)d_in[21];
    const float* W3_10 = (const float*)d_in[22];
    const float* b3_10 = (const float*)d_in[23];
    const float* W3_11 = (const float*)d_in[24];
    const float* b3_11 = (const float*)d_in[25];
    float* out = (float*)d_out;

    init_kernel<<<(N_NODES + 255) / 256, 256>>>();
    edge_kernel<<<HALF_E / 128, 128>>>(
        f0, f1, dist, u, v, wq, wj00, wj01, wj10, wj11,
        rW1, rb1, g1, be1, rW2, rb2, g2, be2,
        W3_00, b3_00, W3_01, b3_01, W3_10, b3_10, W3_11, b3_11);
    exp_kernel<<<(N_EDGES + 255) / 256, 256>>>(v, out);
    norm_kernel<<<HALF_E / 256, 256>>>(v, out);
}